// round 15
// baseline (speedup 1.0000x reference)
#include <cuda_runtime.h>
#include <cuda_bf16.h>
#include <cstdint>
#include <cstddef>

// LSTM encoder: B=128, T=2048, I=64, H=128
// out[0 : B*H) = h_last ; out[B*H : ...) = encoded [B,T,H]
constexpr int B = 128;
constexpr int T = 2048;
constexpr int I = 64;
constexpr int H = 128;
constexpr int G = 4 * H;              // 512 gates

// W_hh register split per gate: KF fp32 k-values + KB bf16 (packed) k-values.
constexpr int KF  = 80;               // fp32 k in registers
constexpr int NPF = KF / 2;           // 40 f32x2 pairs per gate
constexpr int NQF = KF / 4;           // 20 h-quads for fp32 part
constexpr int KB  = H - KF;           // 48 bf16 k in registers
constexpr int NPB = KB / 2;           // 24 packed bf16x2 per gate
constexpr int NQB = KB / 4;           // 12 h-quads for bf16 part

constexpr int NTILES = (B * T) / 64;  // 4096 M-tiles for xproj
constexpr int NCTA_X = 148;           // persistent xproj CTAs

__device__ float g_xp[(size_t)B * T * G + 2 * G];   // padded for overread
__device__ __nv_bfloat16 g_whi[G * I];              // W_ih hi split
__device__ __nv_bfloat16 g_wlo[G * I];              // W_ih lo split

__device__ __forceinline__ void fma2(unsigned long long& d,
                                     unsigned long long a,
                                     unsigned long long b) {
    asm("fma.rn.f32x2 %0, %1, %2, %0;" : "+l"(d) : "l"(a), "l"(b));
}
__device__ __forceinline__ float pair_sum(unsigned long long v) {
    return __uint_as_float((unsigned)v) + __uint_as_float((unsigned)(v >> 32));
}
// expand packed bf16x2 -> packed f32x2 (bf16 = top 16 bits of fp32)
__device__ __forceinline__ unsigned long long bf2_to_f32x2(uint32_t v) {
    uint32_t lo = v << 16;
    uint32_t hi = v & 0xffff0000u;
    unsigned long long r;
    asm("mov.b64 %0, {%1, %2};" : "=l"(r) : "r"(lo), "r"(hi));
    return r;
}
// HW tanh (MUFU.TANH): abs err ~1e-4, validated R12/R13.
__device__ __forceinline__ float tanh_hw(float x) {
    float y;
    asm("tanh.approx.f32 %0, %1;" : "=f"(y) : "f"(x));
    return y;
}
__device__ __forceinline__ float sig_f(float x) {
    return fmaf(0.5f, tanh_hw(0.5f * x), 0.5f);
}
__device__ __forceinline__ void cpasync8(uint32_t smem_addr, const void* gptr) {
    asm volatile("cp.async.ca.shared.global [%0], [%1], 8;\n"
                 :: "r"(smem_addr), "l"(gptr) : "memory");
}
__device__ __forceinline__ void cpasync16(uint32_t smem_addr, const void* gptr) {
    asm volatile("cp.async.cg.shared.global [%0], [%1], 16;\n"
                 :: "r"(smem_addr), "l"(gptr) : "memory");
}
__device__ __forceinline__ uint32_t sw128(uint32_t off) {
    return off ^ ((off >> 3) & 0x70);
}
__device__ __forceinline__ void ldsm_x4(uint32_t* r, uint32_t addr) {
    asm volatile("ldmatrix.sync.aligned.m8n8.x4.shared.b16 {%0,%1,%2,%3}, [%4];"
                 : "=r"(r[0]), "=r"(r[1]), "=r"(r[2]), "=r"(r[3]) : "r"(addr));
}
__device__ __forceinline__ void ldsm_x2(uint32_t* r, uint32_t addr) {
    asm volatile("ldmatrix.sync.aligned.m8n8.x2.shared.b16 {%0,%1}, [%2];"
                 : "=r"(r[0]), "=r"(r[1]) : "r"(addr));
}
__device__ __forceinline__ void mma_bf16(float* c, const uint32_t* a,
                                         const uint32_t* b) {
    asm volatile(
        "mma.sync.aligned.m16n8k16.row.col.f32.bf16.bf16.f32 "
        "{%0,%1,%2,%3}, {%4,%5,%6,%7}, {%8,%9}, {%0,%1,%2,%3};"
        : "+f"(c[0]), "+f"(c[1]), "+f"(c[2]), "+f"(c[3])
        : "r"(a[0]), "r"(a[1]), "r"(a[2]), "r"(a[3]), "r"(b[0]), "r"(b[1]));
}

// ---------------------------------------------------------------------------
// Prep: split W_ih into bf16 hi/lo.
// ---------------------------------------------------------------------------
__global__ void wsplit_kernel(const float* __restrict__ Wih) {
    int i = blockIdx.x * blockDim.x + threadIdx.x;   // 32768 total
    float w = Wih[i];
    __nv_bfloat16 h = __float2bfloat16_rn(w);
    g_whi[i] = h;
    g_wlo[i] = __float2bfloat16_rn(w - __bfloat162float(h));
}

// ---------------------------------------------------------------------------
// x_proj via mma.sync, PERSISTENT: 148 CTAs, W loaded once, ~28 tiles each.
// (unchanged from R13)
// ---------------------------------------------------------------------------
constexpr int SM_BIAS = 0;            // 512 floats (2 KB)
constexpr int SM_RAW  = 2048;         // 64 x 64 fp32 = 16 KB
constexpr int SM_AHI  = 18432;        // 64 rows x 128B = 8 KB (SW128)
constexpr int SM_ALO  = 26624;        // 8 KB
constexpr int SM_BHI  = 34816;        // 512 rows x 128B = 64 KB
constexpr int SM_BLO  = 100352;       // 64 KB
constexpr int SMEM_TC = 165888;       // 162 KB

__global__ void __launch_bounds__(256, 1) xproj_tc_kernel(
    const float* __restrict__ in,
    const float* __restrict__ bih,
    const float* __restrict__ bhh)
{
    extern __shared__ char sm[];
    const int t    = threadIdx.x;
    const int lane = t & 31;
    const int wid  = t >> 5;
    const uint32_t smb = (uint32_t)__cvta_generic_to_shared(sm);
    float* bias_s = (float*)(sm + SM_BIAS);
    float* raw_s  = (float*)(sm + SM_RAW);

    {
        const uint4* shi = (const uint4*)g_whi;
        const uint4* slo = (const uint4*)g_wlo;
#pragma unroll
        for (int it = 0; it < 16; it++) {
            int u = t + it * 256;
            int row = u >> 3, ch = u & 7;
            uint32_t off = sw128(row * 128 + ch * 16);
            *(uint4*)(sm + SM_BHI + off) = shi[u];
            *(uint4*)(sm + SM_BLO + off) = slo[u];
        }
    }
    for (int u = t; u < G; u += 256) bias_s[u] = bih[u] + bhh[u];

    const int wm = wid >> 2, wn = wid & 3;
    const int mbase = wm * 32, nbase = wn * 128;
    const uint32_t a_row  = lane & 15;
    const uint32_t a_koff = (lane >> 4) << 4;
    const uint32_t b_row  = lane & 7;
    const uint32_t b_koff = ((lane >> 3) & 1) << 4;

    int tile = blockIdx.x;
    if (tile < NTILES) {
        const char* src = (const char*)(in + (size_t)tile * 64 * I) + t * 16;
#pragma unroll
        for (int i = 0; i < 4; i++)
            cpasync16(smb + SM_RAW + t * 16 + i * 4096, src + (size_t)i * 4096);
    }
    asm volatile("cp.async.commit_group;\n" ::: "memory");

    for (; tile < NTILES; tile += NCTA_X) {
        const size_t m0 = (size_t)tile * 64;
        asm volatile("cp.async.wait_group 0;\n" ::: "memory");
        __syncthreads();

        {
            const int row = t >> 2, q = t & 3;
            const float4* src = (const float4*)(raw_s + row * I + q * 16);
#pragma unroll
            for (int i = 0; i < 4; i++) {
                float4 v = src[i];
                __nv_bfloat16 h0 = __float2bfloat16_rn(v.x);
                __nv_bfloat16 h1 = __float2bfloat16_rn(v.y);
                __nv_bfloat16 h2 = __float2bfloat16_rn(v.z);
                __nv_bfloat16 h3 = __float2bfloat16_rn(v.w);
                __nv_bfloat162 hp0, hp1, lp0, lp1;
                hp0.x = h0; hp0.y = h1; hp1.x = h2; hp1.y = h3;
                lp0.x = __float2bfloat16_rn(v.x - __bfloat162float(h0));
                lp0.y = __float2bfloat16_rn(v.y - __bfloat162float(h1));
                lp1.x = __float2bfloat16_rn(v.z - __bfloat162float(h2));
                lp1.y = __float2bfloat16_rn(v.w - __bfloat162float(h3));
                uint32_t b0 = row * 128 + q * 32 + i * 8;
                *(uint32_t*)(sm + SM_AHI + sw128(b0))     = *(uint32_t*)&hp0;
                *(uint32_t*)(sm + SM_AHI + sw128(b0 + 4)) = *(uint32_t*)&hp1;
                *(uint32_t*)(sm + SM_ALO + sw128(b0))     = *(uint32_t*)&lp0;
                *(uint32_t*)(sm + SM_ALO + sw128(b0 + 4)) = *(uint32_t*)&lp1;
            }
        }
        __syncthreads();

        if (tile + NCTA_X < NTILES) {
            const char* src =
                (const char*)(in + (size_t)(tile + NCTA_X) * 64 * I) + t * 16;
#pragma unroll
            for (int i = 0; i < 4; i++)
                cpasync16(smb + SM_RAW + t * 16 + i * 4096, src + (size_t)i * 4096);
        }
        asm volatile("cp.async.commit_group;\n" ::: "memory");

        float acc[2][16][4];
#pragma unroll
        for (int mt = 0; mt < 2; mt++)
#pragma unroll
            for (int nt = 0; nt < 16; nt++)
#pragma unroll
                for (int r = 0; r < 4; r++) acc[mt][nt][r] = 0.f;

#pragma unroll
        for (int pass = 0; pass < 3; pass++) {
            const uint32_t Ab = smb + (pass == 2 ? SM_ALO : SM_AHI);
            const uint32_t Bb = smb + (pass == 1 ? SM_BLO : SM_BHI);
#pragma unroll
            for (int ks = 0; ks < 4; ks++) {
                uint32_t afr[2][4];
#pragma unroll
                for (int mt = 0; mt < 2; mt++) {
                    uint32_t off = (mbase + mt * 16 + a_row) * 128 + ks * 32 + a_koff;
                    ldsm_x4(afr[mt], Ab + sw128(off));
                }
#pragma unroll
                for (int nt = 0; nt < 16; nt++) {
                    uint32_t boff = (nbase + nt * 8 + b_row) * 128 + ks * 32 + b_koff;
                    uint32_t bfr[2];
                    ldsm_x2(bfr, Bb + sw128(boff));
                    mma_bf16(acc[0][nt], afr[0], bfr);
                    mma_bf16(acc[1][nt], afr[1], bfr);
                }
            }
        }

        {
            const int r0 = lane >> 2;
            const int cq = 2 * (lane & 3);
#pragma unroll
            for (int mt = 0; mt < 2; mt++) {
                size_t row = m0 + mbase + mt * 16 + r0;
#pragma unroll
                for (int nt = 0; nt < 16; nt++) {
                    int col = nbase + nt * 8 + cq;
                    float b0 = bias_s[col], b1 = bias_s[col + 1];
                    *(float2*)(g_xp + row * G + col) =
                        make_float2(acc[mt][nt][0] + b0, acc[mt][nt][1] + b1);
                    *(float2*)(g_xp + (row + 8) * G + col) =
                        make_float2(acc[mt][nt][2] + b0, acc[mt][nt][3] + b1);
                }
            }
        }
        __syncthreads();
    }
}

// ---------------------------------------------------------------------------
// Recurrence: R13 structure; ALL W_hh in registers (80 fp32 + 48 bf16-packed
// k-values per gate). Zero smem weight traffic per step.
// ---------------------------------------------------------------------------
__global__ void __launch_bounds__(256, 1) lstm_kernel(
    const float* __restrict__ h0,
    const float* __restrict__ c0,
    const float* __restrict__ Whh,
    float* __restrict__ out)
{
    extern __shared__ float smem[];
    float*  h_s  = smem;                                // 128 floats
    float2* ex_s = (float2*)(h_s + H);                  // 128 float2
    float*  xb   = (float*)(ex_s + H);                  // 4 * G floats (8 KB)

    const int tid  = threadIdx.x;
    const int half = tid >> 7;
    const int j    = tid & 127;
    const int g0   = (half << 8) + j;    // i (A) / g (B)
    const int g1   = g0 + 128;           // f (A) / o (B)
    const int b    = blockIdx.x;

    // v0 = ee * tanh_hw(ff * p0) + gg :  A = sigmoid, B = tanh
    const float ee = half ? 1.f : 0.5f;
    const float ff = half ? 1.f : 0.5f;
    const float gg = half ? 0.f : 0.5f;

    // fp32 weight registers: k in [0, KF)
    unsigned long long w0[NPF], w1[NPF];
    {
        const unsigned long long* r0 = (const unsigned long long*)(Whh + (size_t)g0 * H);
        const unsigned long long* r1 = (const unsigned long long*)(Whh + (size_t)g1 * H);
#pragma unroll
        for (int i = 0; i < NPF; i++) { w0[i] = r0[i]; w1[i] = r1[i]; }
    }
    // bf16 packed weight registers: k in [KF, 128)
    uint32_t w0b[NPB], w1b[NPB];
    {
        const float2* r0 = (const float2*)(Whh + (size_t)g0 * H + KF);
        const float2* r1 = (const float2*)(Whh + (size_t)g1 * H + KF);
#pragma unroll
        for (int i = 0; i < NPB; i++) {
            float2 a = r0[i], bq = r1[i];
            __nv_bfloat162 pa, pb;
            pa.x = __float2bfloat16_rn(a.x);  pa.y = __float2bfloat16_rn(a.y);
            pb.x = __float2bfloat16_rn(bq.x); pb.y = __float2bfloat16_rn(bq.y);
            w0b[i] = *(uint32_t*)&pa;
            w1b[i] = *(uint32_t*)&pb;
        }
    }

    float c = 0.f, hn_last = 0.f;
    if (half == 0) {
        c = c0[b * H + j];
        h_s[j] = h0[b * H + j];
    }

    const char* gx = (const char*)(g_xp + (size_t)b * T * G + tid * 2);
    const uint32_t xb_base = (uint32_t)__cvta_generic_to_shared(xb) + tid * 8u;

    cpasync8(xb_base + 0 * G * 4, gx);  gx += (size_t)G * 4;
    asm volatile("cp.async.commit_group;\n" ::: "memory");
    cpasync8(xb_base + 1 * G * 4, gx);  gx += (size_t)G * 4;
    asm volatile("cp.async.commit_group;\n" ::: "memory");
    asm volatile("cp.async.wait_group 0;\n" ::: "memory");

    __syncthreads();

    float* enc = out + (size_t)B * H + (size_t)b * T * H;

    for (int t = 0; t < T; t++) {
        cpasync8(xb_base + ((t + 2) & 3) * G * 4, gx);
        gx += (size_t)G * 4;
        asm volatile("cp.async.commit_group;\n" ::: "memory");

        unsigned long long a0 = 0ull, a1 = 0ull, b0 = 0ull, b1 = 0ull;
        const ulonglong2* h2 = (const ulonglong2*)h_s;

#pragma unroll
        for (int q = 0; q < NQF; q++) {               // k in [0,80), fp32 regs
            ulonglong2 hv = h2[q];
            fma2(a0, w0[2 * q],     hv.x);
            fma2(a1, w0[2 * q + 1], hv.y);
            fma2(b0, w1[2 * q],     hv.x);
            fma2(b1, w1[2 * q + 1], hv.y);
        }
#pragma unroll
        for (int q = 0; q < NQB; q++) {               // k in [80,128), bf16 regs
            ulonglong2 hv = h2[NQF + q];
            fma2(a0, bf2_to_f32x2(w0b[2 * q]),     hv.x);
            fma2(a1, bf2_to_f32x2(w0b[2 * q + 1]), hv.y);
            fma2(b0, bf2_to_f32x2(w1b[2 * q]),     hv.x);
            fma2(b1, bf2_to_f32x2(w1b[2 * q + 1]), hv.y);
        }

        const float* xrow = xb + (t & 3) * G;
        float p0 = pair_sum(a0) + pair_sum(a1) + xrow[g0];
        float p1 = pair_sum(b0) + pair_sum(b1) + xrow[g1];

        // A: v0 = sig(i), v1 = sig(f) ; B: v0 = tanh(g), v1 = sig(o)
        float v0 = fmaf(ee, tanh_hw(ff * p0), gg);
        float v1 = sig_f(p1);

        if (half) ex_s[j] = make_float2(v0, v1);
        __syncthreads();

        if (!half) {
            float2 go = ex_s[j];
            c = v1 * c + v0 * go.x;              // sig(f)*c + sig(i)*tanh(g)
            float hn = go.y * tanh_hw(c);
            h_s[j] = hn;
            enc[(size_t)t * H + j] = hn;
            hn_last = hn;
        }

        asm volatile("cp.async.wait_group 1;\n" ::: "memory");
        __syncthreads();
    }

    if (half == 0) out[b * H + j] = hn_last;
}

// ---------------------------------------------------------------------------
extern "C" void kernel_launch(void* const* d_in, const int* in_sizes, int n_in,
                              void* d_out, int out_size) {
    const float* input = (const float*)d_in[0];
    const float* h0    = (const float*)d_in[1];
    const float* c0    = (const float*)d_in[2];
    const float* Wih   = (const float*)d_in[3];
    const float* Whh   = (const float*)d_in[4];
    const float* bih   = (const float*)d_in[5];
    const float* bhh   = (const float*)d_in[6];
    float* out = (float*)d_out;

    constexpr int SMEM2 = H * (int)sizeof(float)
                        + H * (int)sizeof(float2)
                        + 4 * G * (int)sizeof(float);       // ~9.7 KB
    cudaFuncSetAttribute(lstm_kernel,
                         cudaFuncAttributeMaxDynamicSharedMemorySize, SMEM2);
    cudaFuncSetAttribute(xproj_tc_kernel,
                         cudaFuncAttributeMaxDynamicSharedMemorySize, SMEM_TC);

    wsplit_kernel<<<(G * I) / 256, 256>>>(Wih);
    xproj_tc_kernel<<<NCTA_X, 256, SMEM_TC>>>(input, bih, bhh);
    lstm_kernel<<<B, 256, SMEM2>>>(h0, c0, Whh, out);
}

// round 16
// speedup vs baseline: 2.5712x; 2.5712x over previous
#include <cuda_runtime.h>
#include <cuda_bf16.h>
#include <cstdint>
#include <cstddef>

// LSTM encoder: B=128, T=2048, I=64, H=128
// out[0 : B*H) = h_last ; out[B*H : ...) = encoded [B,T,H]
constexpr int B = 128;
constexpr int T = 2048;
constexpr int I = 64;
constexpr int H = 128;
constexpr int G = 4 * H;              // 512 gates
constexpr int KREG = 104;             // W_hh k-values in fp32 registers per gate
constexpr int NP   = KREG / 2;        // 52 f32x2 pairs per gate
constexpr int NQR  = KREG / 4;        // 26 register h-quads
constexpr int KSM  = H - KREG;        // 24 k-values in smem (bf16)
constexpr int NCH  = KSM / 8;         // 3 bf16 chunks of 8 k per gate

constexpr int NTILES = (B * T) / 64;  // 4096 M-tiles for xproj
constexpr int NCTA_X = 148;           // persistent xproj CTAs

__device__ float g_xp[(size_t)B * T * G + 2 * G];   // padded for overread
__device__ __nv_bfloat16 g_whi[G * I];              // W_ih hi split
__device__ __nv_bfloat16 g_wlo[G * I];              // W_ih lo split

__device__ __forceinline__ void fma2(unsigned long long& d,
                                     unsigned long long a,
                                     unsigned long long b) {
    asm("fma.rn.f32x2 %0, %1, %2, %0;" : "+l"(d) : "l"(a), "l"(b));
}
__device__ __forceinline__ unsigned long long add2(unsigned long long a,
                                                   unsigned long long b) {
    unsigned long long r;
    asm("add.rn.f32x2 %0, %1, %2;" : "=l"(r) : "l"(a), "l"(b));
    return r;
}
__device__ __forceinline__ float pair_sum(unsigned long long v) {
    return __uint_as_float((unsigned)v) + __uint_as_float((unsigned)(v >> 32));
}
// expand packed bf16x2 -> packed f32x2 (bf16 = top 16 bits of fp32)
__device__ __forceinline__ unsigned long long bf2_to_f32x2(uint32_t v) {
    uint32_t lo = v << 16;
    uint32_t hi = v & 0xffff0000u;
    unsigned long long r;
    asm("mov.b64 %0, {%1, %2};" : "=l"(r) : "r"(lo), "r"(hi));
    return r;
}
// HW tanh (MUFU.TANH): abs err ~1e-4, validated R12/R13.
__device__ __forceinline__ float tanh_hw(float x) {
    float y;
    asm("tanh.approx.f32 %0, %1;" : "=f"(y) : "f"(x));
    return y;
}
__device__ __forceinline__ float sig_f(float x) {
    return fmaf(0.5f, tanh_hw(0.5f * x), 0.5f);
}
__device__ __forceinline__ void cpasync8(uint32_t smem_addr, const void* gptr) {
    asm volatile("cp.async.ca.shared.global [%0], [%1], 8;\n"
                 :: "r"(smem_addr), "l"(gptr) : "memory");
}
__device__ __forceinline__ void cpasync16(uint32_t smem_addr, const void* gptr) {
    asm volatile("cp.async.cg.shared.global [%0], [%1], 16;\n"
                 :: "r"(smem_addr), "l"(gptr) : "memory");
}
__device__ __forceinline__ uint32_t sw128(uint32_t off) {
    return off ^ ((off >> 3) & 0x70);
}
__device__ __forceinline__ void ldsm_x4(uint32_t* r, uint32_t addr) {
    asm volatile("ldmatrix.sync.aligned.m8n8.x4.shared.b16 {%0,%1,%2,%3}, [%4];"
                 : "=r"(r[0]), "=r"(r[1]), "=r"(r[2]), "=r"(r[3]) : "r"(addr));
}
__device__ __forceinline__ void ldsm_x2(uint32_t* r, uint32_t addr) {
    asm volatile("ldmatrix.sync.aligned.m8n8.x2.shared.b16 {%0,%1}, [%2];"
                 : "=r"(r[0]), "=r"(r[1]) : "r"(addr));
}
__device__ __forceinline__ void mma_bf16(float* c, const uint32_t* a,
                                         const uint32_t* b) {
    asm volatile(
        "mma.sync.aligned.m16n8k16.row.col.f32.bf16.bf16.f32 "
        "{%0,%1,%2,%3}, {%4,%5,%6,%7}, {%8,%9}, {%0,%1,%2,%3};"
        : "+f"(c[0]), "+f"(c[1]), "+f"(c[2]), "+f"(c[3])
        : "r"(a[0]), "r"(a[1]), "r"(a[2]), "r"(a[3]), "r"(b[0]), "r"(b[1]));
}

// ---------------------------------------------------------------------------
// Prep: split W_ih into bf16 hi/lo.
// ---------------------------------------------------------------------------
__global__ void wsplit_kernel(const float* __restrict__ Wih) {
    int i = blockIdx.x * blockDim.x + threadIdx.x;   // 32768 total
    float w = Wih[i];
    __nv_bfloat16 h = __float2bfloat16_rn(w);
    g_whi[i] = h;
    g_wlo[i] = __float2bfloat16_rn(w - __bfloat162float(h));
}

// ---------------------------------------------------------------------------
// x_proj via mma.sync, PERSISTENT: 148 CTAs, W loaded once, ~28 tiles each.
// (unchanged from R13)
// ---------------------------------------------------------------------------
constexpr int SM_BIAS = 0;            // 512 floats (2 KB)
constexpr int SM_RAW  = 2048;         // 64 x 64 fp32 = 16 KB
constexpr int SM_AHI  = 18432;        // 64 rows x 128B = 8 KB (SW128)
constexpr int SM_ALO  = 26624;        // 8 KB
constexpr int SM_BHI  = 34816;        // 512 rows x 128B = 64 KB
constexpr int SM_BLO  = 100352;       // 64 KB
constexpr int SMEM_TC = 165888;       // 162 KB

__global__ void __launch_bounds__(256, 1) xproj_tc_kernel(
    const float* __restrict__ in,
    const float* __restrict__ bih,
    const float* __restrict__ bhh)
{
    extern __shared__ char sm[];
    const int t    = threadIdx.x;
    const int lane = t & 31;
    const int wid  = t >> 5;
    const uint32_t smb = (uint32_t)__cvta_generic_to_shared(sm);
    float* bias_s = (float*)(sm + SM_BIAS);
    float* raw_s  = (float*)(sm + SM_RAW);

    {
        const uint4* shi = (const uint4*)g_whi;
        const uint4* slo = (const uint4*)g_wlo;
#pragma unroll
        for (int it = 0; it < 16; it++) {
            int u = t + it * 256;
            int row = u >> 3, ch = u & 7;
            uint32_t off = sw128(row * 128 + ch * 16);
            *(uint4*)(sm + SM_BHI + off) = shi[u];
            *(uint4*)(sm + SM_BLO + off) = slo[u];
        }
    }
    for (int u = t; u < G; u += 256) bias_s[u] = bih[u] + bhh[u];

    const int wm = wid >> 2, wn = wid & 3;
    const int mbase = wm * 32, nbase = wn * 128;
    const uint32_t a_row  = lane & 15;
    const uint32_t a_koff = (lane >> 4) << 4;
    const uint32_t b_row  = lane & 7;
    const uint32_t b_koff = ((lane >> 3) & 1) << 4;

    int tile = blockIdx.x;
    if (tile < NTILES) {
        const char* src = (const char*)(in + (size_t)tile * 64 * I) + t * 16;
#pragma unroll
        for (int i = 0; i < 4; i++)
            cpasync16(smb + SM_RAW + t * 16 + i * 4096, src + (size_t)i * 4096);
    }
    asm volatile("cp.async.commit_group;\n" ::: "memory");

    for (; tile < NTILES; tile += NCTA_X) {
        const size_t m0 = (size_t)tile * 64;
        asm volatile("cp.async.wait_group 0;\n" ::: "memory");
        __syncthreads();

        {
            const int row = t >> 2, q = t & 3;
            const float4* src = (const float4*)(raw_s + row * I + q * 16);
#pragma unroll
            for (int i = 0; i < 4; i++) {
                float4 v = src[i];
                __nv_bfloat16 h0 = __float2bfloat16_rn(v.x);
                __nv_bfloat16 h1 = __float2bfloat16_rn(v.y);
                __nv_bfloat16 h2 = __float2bfloat16_rn(v.z);
                __nv_bfloat16 h3 = __float2bfloat16_rn(v.w);
                __nv_bfloat162 hp0, hp1, lp0, lp1;
                hp0.x = h0; hp0.y = h1; hp1.x = h2; hp1.y = h3;
                lp0.x = __float2bfloat16_rn(v.x - __bfloat162float(h0));
                lp0.y = __float2bfloat16_rn(v.y - __bfloat162float(h1));
                lp1.x = __float2bfloat16_rn(v.z - __bfloat162float(h2));
                lp1.y = __float2bfloat16_rn(v.w - __bfloat162float(h3));
                uint32_t b0 = row * 128 + q * 32 + i * 8;
                *(uint32_t*)(sm + SM_AHI + sw128(b0))     = *(uint32_t*)&hp0;
                *(uint32_t*)(sm + SM_AHI + sw128(b0 + 4)) = *(uint32_t*)&hp1;
                *(uint32_t*)(sm + SM_ALO + sw128(b0))     = *(uint32_t*)&lp0;
                *(uint32_t*)(sm + SM_ALO + sw128(b0 + 4)) = *(uint32_t*)&lp1;
            }
        }
        __syncthreads();

        if (tile + NCTA_X < NTILES) {
            const char* src =
                (const char*)(in + (size_t)(tile + NCTA_X) * 64 * I) + t * 16;
#pragma unroll
            for (int i = 0; i < 4; i++)
                cpasync16(smb + SM_RAW + t * 16 + i * 4096, src + (size_t)i * 4096);
        }
        asm volatile("cp.async.commit_group;\n" ::: "memory");

        float acc[2][16][4];
#pragma unroll
        for (int mt = 0; mt < 2; mt++)
#pragma unroll
            for (int nt = 0; nt < 16; nt++)
#pragma unroll
                for (int r = 0; r < 4; r++) acc[mt][nt][r] = 0.f;

#pragma unroll
        for (int pass = 0; pass < 3; pass++) {
            const uint32_t Ab = smb + (pass == 2 ? SM_ALO : SM_AHI);
            const uint32_t Bb = smb + (pass == 1 ? SM_BLO : SM_BHI);
#pragma unroll
            for (int ks = 0; ks < 4; ks++) {
                uint32_t afr[2][4];
#pragma unroll
                for (int mt = 0; mt < 2; mt++) {
                    uint32_t off = (mbase + mt * 16 + a_row) * 128 + ks * 32 + a_koff;
                    ldsm_x4(afr[mt], Ab + sw128(off));
                }
#pragma unroll
                for (int nt = 0; nt < 16; nt++) {
                    uint32_t boff = (nbase + nt * 8 + b_row) * 128 + ks * 32 + b_koff;
                    uint32_t bfr[2];
                    ldsm_x2(bfr, Bb + sw128(boff));
                    mma_bf16(acc[0][nt], afr[0], bfr);
                    mma_bf16(acc[1][nt], afr[1], bfr);
                }
            }
        }

        {
            const int r0 = lane >> 2;
            const int cq = 2 * (lane & 3);
#pragma unroll
            for (int mt = 0; mt < 2; mt++) {
                size_t row = m0 + mbase + mt * 16 + r0;
#pragma unroll
                for (int nt = 0; nt < 16; nt++) {
                    int col = nbase + nt * 8 + cq;
                    float b0 = bias_s[col], b1 = bias_s[col + 1];
                    *(float2*)(g_xp + row * G + col) =
                        make_float2(acc[mt][nt][0] + b0, acc[mt][nt][1] + b1);
                    *(float2*)(g_xp + (row + 8) * G + col) =
                        make_float2(acc[mt][nt][2] + b0, acc[mt][nt][3] + b1);
                }
            }
        }
        __syncthreads();
    }
}

// ---------------------------------------------------------------------------
// Recurrence: R13 structure (best: 208 fp32 weight regs + 24 bf16 k in smem)
// + packed accumulator combine + split exchange barrier (B arrives, A syncs).
// ---------------------------------------------------------------------------
__global__ void __launch_bounds__(256, 1) lstm_kernel(
    const float* __restrict__ h0,
    const float* __restrict__ c0,
    const float* __restrict__ Whh,
    float* __restrict__ out)
{
    extern __shared__ float smem[];
    // Wsb[ch][g]: uint4 = 8 bf16 weights (k = KREG + 8*ch .. +7) of gate g
    uint4*  Wsb  = (uint4*)smem;                        // 3*512*16 = 24 KB
    float*  h_s  = smem + NCH * G * 4;                  // 128 floats
    float2* ex_s = (float2*)(h_s + H);                  // 128 float2
    float*  xb   = (float*)(ex_s + H);                  // 4 * G floats (8 KB)

    const int tid  = threadIdx.x;
    const int half = tid >> 7;
    const int j    = tid & 127;
    const int g0   = (half << 8) + j;    // i (A) / g (B)
    const int g1   = g0 + 128;           // f (A) / o (B)
    const int b    = blockIdx.x;

    // v0 = ee * tanh_hw(ff * p0) + gg :  A = sigmoid, B = tanh
    const float ee = half ? 1.f : 0.5f;
    const float ff = half ? 1.f : 0.5f;
    const float gg = half ? 0.f : 0.5f;

    {   // build bf16 smem weight slice for this thread's two gates
        const float2* r0 = (const float2*)(Whh + (size_t)g0 * H + KREG);
        const float2* r1 = (const float2*)(Whh + (size_t)g1 * H + KREG);
#pragma unroll
        for (int ch = 0; ch < NCH; ch++) {
            uint32_t p0[4], p1[4];
#pragma unroll
            for (int e = 0; e < 4; e++) {
                float2 wa = r0[ch * 4 + e];
                float2 wb = r1[ch * 4 + e];
                __nv_bfloat162 ba, bbv;
                ba.x  = __float2bfloat16_rn(wa.x);
                ba.y  = __float2bfloat16_rn(wa.y);
                bbv.x = __float2bfloat16_rn(wb.x);
                bbv.y = __float2bfloat16_rn(wb.y);
                p0[e] = *(uint32_t*)&ba;
                p1[e] = *(uint32_t*)&bbv;
            }
            Wsb[ch * G + g0] = make_uint4(p0[0], p0[1], p0[2], p0[3]);
            Wsb[ch * G + g1] = make_uint4(p1[0], p1[1], p1[2], p1[3]);
        }
    }

    unsigned long long w0[NP], w1[NP];
    {
        const unsigned long long* r0 = (const unsigned long long*)(Whh + (size_t)g0 * H);
        const unsigned long long* r1 = (const unsigned long long*)(Whh + (size_t)g1 * H);
#pragma unroll
        for (int i = 0; i < NP; i++) { w0[i] = r0[i]; w1[i] = r1[i]; }
    }

    float c = 0.f, hn_last = 0.f;
    if (half == 0) {
        c = c0[b * H + j];
        h_s[j] = h0[b * H + j];
    }

    const char* gx = (const char*)(g_xp + (size_t)b * T * G + tid * 2);
    const uint32_t xb_base = (uint32_t)__cvta_generic_to_shared(xb) + tid * 8u;

    cpasync8(xb_base + 0 * G * 4, gx);  gx += (size_t)G * 4;
    asm volatile("cp.async.commit_group;\n" ::: "memory");
    cpasync8(xb_base + 1 * G * 4, gx);  gx += (size_t)G * 4;
    asm volatile("cp.async.commit_group;\n" ::: "memory");
    asm volatile("cp.async.wait_group 0;\n" ::: "memory");

    __syncthreads();

    float* enc = out + (size_t)B * H + (size_t)b * T * H;

    for (int t = 0; t < T; t++) {
        cpasync8(xb_base + ((t + 2) & 3) * G * 4, gx);
        gx += (size_t)G * 4;
        asm volatile("cp.async.commit_group;\n" ::: "memory");

        unsigned long long a0 = 0ull, a1 = 0ull, b0 = 0ull, b1 = 0ull;
        const ulonglong2* h2 = (const ulonglong2*)h_s;

#pragma unroll
        for (int q = 0; q < NQR; q++) {               // k in [0,104), fp32 regs
            ulonglong2 hv = h2[q];
            fma2(a0, w0[2 * q],     hv.x);
            fma2(a1, w0[2 * q + 1], hv.y);
            fma2(b0, w1[2 * q],     hv.x);
            fma2(b1, w1[2 * q + 1], hv.y);
        }
#pragma unroll
        for (int ch = 0; ch < NCH; ch++) {            // k in [104,128), bf16 smem
            ulonglong2 hv0 = h2[NQR + 2 * ch];
            ulonglong2 hv1 = h2[NQR + 2 * ch + 1];
            uint4 wa = Wsb[ch * G + g0];
            uint4 wb = Wsb[ch * G + g1];
            fma2(a0, bf2_to_f32x2(wa.x), hv0.x);
            fma2(a1, bf2_to_f32x2(wa.y), hv0.y);
            fma2(a0, bf2_to_f32x2(wa.z), hv1.x);
            fma2(a1, bf2_to_f32x2(wa.w), hv1.y);
            fma2(b0, bf2_to_f32x2(wb.x), hv0.x);
            fma2(b1, bf2_to_f32x2(wb.y), hv0.y);
            fma2(b0, bf2_to_f32x2(wb.z), hv1.x);
            fma2(b1, bf2_to_f32x2(wb.w), hv1.y);
        }

        const float* xrow = xb + (t & 3) * G;
        // packed combine: one f32x2 add, one pair_sum each
        float p0 = pair_sum(add2(a0, a1)) + xrow[g0];
        float p1 = pair_sum(add2(b0, b1)) + xrow[g1];

        // A: v0 = sig(i), v1 = sig(f) ; B: v0 = tanh(g), v1 = sig(o)
        float v0 = fmaf(ee, tanh_hw(ff * p0), gg);
        float v1 = sig_f(p1);

        if (half) {
            ex_s[j] = make_float2(v0, v1);
            asm volatile("bar.arrive 1, 256;" ::: "memory");   // non-blocking
        } else {
            asm volatile("bar.sync 1, 256;" ::: "memory");     // all reads done
            float2 go = ex_s[j];
            c = v1 * c + v0 * go.x;              // sig(f)*c + sig(i)*tanh(g)
            float hn = go.y * tanh_hw(c);
            h_s[j] = hn;
            enc[(size_t)t * H + j] = hn;
            hn_last = hn;
        }

        asm volatile("cp.async.wait_group 1;\n" ::: "memory");
        __syncthreads();      // publish h_s + staged x
    }

    if (half == 0) out[b * H + j] = hn_last;
}

// ---------------------------------------------------------------------------
extern "C" void kernel_launch(void* const* d_in, const int* in_sizes, int n_in,
                              void* d_out, int out_size) {
    const float* input = (const float*)d_in[0];
    const float* h0    = (const float*)d_in[1];
    const float* c0    = (const float*)d_in[2];
    const float* Wih   = (const float*)d_in[3];
    const float* Whh   = (const float*)d_in[4];
    const float* bih   = (const float*)d_in[5];
    const float* bhh   = (const float*)d_in[6];
    float* out = (float*)d_out;

    constexpr int SMEM2 = (NCH * G * 4 + H) * (int)sizeof(float)
                        + H * (int)sizeof(float2)
                        + 4 * G * (int)sizeof(float);       // ~34 KB
    cudaFuncSetAttribute(lstm_kernel,
                         cudaFuncAttributeMaxDynamicSharedMemorySize, SMEM2);
    cudaFuncSetAttribute(xproj_tc_kernel,
                         cudaFuncAttributeMaxDynamicSharedMemorySize, SMEM_TC);

    wsplit_kernel<<<(G * I) / 256, 256>>>(Wih);
    xproj_tc_kernel<<<NCTA_X, 256, SMEM_TC>>>(input, bih, bhh);
    lstm_kernel<<<B, 256, SMEM2>>>(h0, c0, Whh, out);
}